// round 16
// baseline (speedup 1.0000x reference)
#include <cuda_runtime.h>
#include <cuda_fp16.h>
#include <cstdint>

#define BATCH  256
#define EDIM   512
#define NNODES 16383
#define NPAD   16384

// ---------------------------------------------------------------------------
// Scratch (static device globals: allocation-free rule)
// ---------------------------------------------------------------------------
__device__ float g_S[BATCH * NPAD];   // delta logits

// ---------------------------------------------------------------------------
// cp.async + ldmatrix helpers
// ---------------------------------------------------------------------------
__device__ __forceinline__ uint32_t smem_u32(const void* p) {
    uint32_t a;
    asm("{ .reg .u64 t; cvta.to.shared.u64 t, %1; cvt.u32.u64 %0, t; }" : "=r"(a) : "l"(p));
    return a;
}
__device__ __forceinline__ void cp16(uint32_t dst, const void* src) {
    asm volatile("cp.async.ca.shared.global [%0], [%1], 16;" :: "r"(dst), "l"(src));
}
__device__ __forceinline__ void cp16z(uint32_t dst, const void* src, uint32_t src_bytes) {
    asm volatile("cp.async.ca.shared.global [%0], [%1], 16, %2;"
                 :: "r"(dst), "l"(src), "r"(src_bytes));
}
#define CP_COMMIT() asm volatile("cp.async.commit_group;" ::: "memory")
#define CP_WAIT0()  asm volatile("cp.async.wait_group 0;" ::: "memory")

__device__ __forceinline__ void ldsm4(uint32_t* r, uint32_t addr) {
    asm volatile("ldmatrix.sync.aligned.m8n8.x4.shared.b16 {%0,%1,%2,%3}, [%4];"
                 : "=r"(r[0]), "=r"(r[1]), "=r"(r[2]), "=r"(r[3]) : "r"(addr));
}

// f16-accumulator MMA: D,C fp16 (2 regs = 4 halves)
__device__ __forceinline__ void mma16816h(uint32_t* acc, const uint32_t* a,
                                          uint32_t b0, uint32_t b1) {
    asm volatile(
        "mma.sync.aligned.m16n8k16.row.col.f16.f16.f16.f16 "
        "{%0,%1}, {%2,%3,%4,%5}, {%6,%7}, {%0,%1};\n"
        : "+r"(acc[0]), "+r"(acc[1])
        : "r"(a[0]), "r"(a[1]), "r"(a[2]), "r"(a[3]), "r"(b0), "r"(b1));
}

// ---------------------------------------------------------------------------
// Single-phase fp16 GEMM, f16 accumulators promoted to f32 every K=64.
//   256 threads / 8 warps; warp tile 64(M) x 64(N). Block M=256 x N=128.
//   K = 512 in 16 chunks of 32; 2-stage cp.async ring; x and W converted
//   to fp16 in-SMEM (both raw f32 staged via cp.async).
// ---------------------------------------------------------------------------
#define STAGE     96256
#define OFF_AT    0          // A fp16 tile: 256 x 40 (pitch 80 B) = 20480
#define OFF_BT    20480      // B fp16 tile: 128 x 40 = 10240
#define OFF_XR    30720      // raw x: 256 rows x 32 f32 = 32768
#define OFF_WR    63488      // raw W: 128 nodes x 64 f32 = 32768
#define OFF_DB    (2 * STAGE)            // 192512
#define GEMM_SMEM (OFF_DB + 512)         // 193024 B

__global__ void __launch_bounds__(256) gemm_f(const float* __restrict__ x,
                                              const float* __restrict__ W,
                                              const float* __restrict__ bvec) {
    extern __shared__ char smem[];
    const uint32_t sb = smem_u32(smem);
    const int tid  = threadIdx.x;
    const int lane = tid & 31;
    const int warp = tid >> 5;
    const int wm   = warp >> 1;   // 0..3 -> M base wm*64
    const int wn   = warp & 1;    // 0..1 -> N base wn*64
    const int ntile = blockIdx.x * 128;

    float* db_s = reinterpret_cast<float*>(smem + OFF_DB);
    if (tid < 128) {
        int col = ntile + tid;
        db_s[tid] = (col < NNODES) ? (bvec[2 * col + 1] - bvec[2 * col]) : 0.f;
    }

    float    acc[4][8][4];      // f32 master accumulators
    uint32_t accH[4][8][2];     // f16 partial accumulators (f16x2 pairs)
#pragma unroll
    for (int mi = 0; mi < 4; ++mi)
#pragma unroll
        for (int ni = 0; ni < 8; ++ni) {
#pragma unroll
            for (int q = 0; q < 4; ++q) acc[mi][ni][q] = 0.f;
            accH[mi][ni][0] = 0u;
            accH[mi][ni][1] = 0u;
        }

    // ldmatrix per-lane address components
    const int a_row = wm * 64 + (lane & 7) + ((lane >> 3) & 1) * 8;
    const int a_col = (lane >> 4) * 8;
    const int b_row = wn * 64 + (lane & 7) + ((lane >> 4) & 1) * 8;
    const int b_col = ((lane >> 3) & 1) * 8;

    // ---- issue async loads for chunk c into stage c&1 ----
    auto issue = [&](int c) {
        const uint32_t stg = sb + (uint32_t)(c & 1) * STAGE;
        // raw x: 256 rows x 32 f32 (8 x 16 B) = 2048 cp16, 8/thread
#pragma unroll
        for (int j = 0; j < 8; ++j) {
            int u  = tid + 256 * j;
            int row = u >> 3;
            int q8  = u & 7;
            const char* src = reinterpret_cast<const char*>(x) +
                              (size_t)row * 2048 + c * 128 + q8 * 16;
            cp16(stg + OFF_XR + u * 16, src);
        }
        // raw W: 128 nodes x 64 f32 (16 x 16 B) = 2048 cp16, 8/thread
#pragma unroll
        for (int j = 0; j < 8; ++j) {
            int p  = tid + 256 * j;
            int nl = p >> 4;
            int e2 = p & 15;
            int ng = ntile + nl;
            int ok = (ng < NNODES);
            const char* src = reinterpret_cast<const char*>(
                W + (size_t)(ok ? ng : 0) * 1024 + c * 64) + e2 * 16;
            cp16z(stg + OFF_WR + p * 16, src, ok ? 16u : 0u);
        }
        CP_COMMIT();
    };

    // ---- convert raw f32 -> fp16 tiles (same-thread chunks) ----
    auto convert = [&](int c) {
        char* base = smem + (size_t)(c & 1) * STAGE;
#pragma unroll
        for (int j = 0; j < 8; ++j) {
            int u  = tid + 256 * j;
            int row = u >> 3;
            int q8  = u & 7;
            float4 v = *reinterpret_cast<const float4*>(base + OFF_XR + u * 16);
            __half2 p0 = __halves2half2(__float2half_rn(v.x), __float2half_rn(v.y));
            __half2 p1 = __halves2half2(__float2half_rn(v.z), __float2half_rn(v.w));
            __half2* dst = reinterpret_cast<__half2*>(base + OFF_AT + row * 80 + q8 * 8);
            dst[0] = p0;
            dst[1] = p1;
        }
#pragma unroll
        for (int j = 0; j < 8; ++j) {
            int p  = tid + 256 * j;
            int nl = p >> 4;
            int e2 = p & 15;
            float4 w = *reinterpret_cast<const float4*>(base + OFF_WR + p * 16);
            __half h0 = __float2half_rn(w.y - w.x);
            __half h1 = __float2half_rn(w.w - w.z);
            *reinterpret_cast<__half2*>(base + OFF_BT + nl * 80 + e2 * 4) =
                __halves2half2(h0, h1);
        }
    };

    // ---- promote f16 partials into f32 accumulators, reset f16 ----
    auto promote = [&]() {
#pragma unroll
        for (int mi = 0; mi < 4; ++mi)
#pragma unroll
            for (int ni = 0; ni < 8; ++ni) {
                float2 f0 = __half22float2(*reinterpret_cast<__half2*>(&accH[mi][ni][0]));
                float2 f1 = __half22float2(*reinterpret_cast<__half2*>(&accH[mi][ni][1]));
                acc[mi][ni][0] += f0.x;
                acc[mi][ni][1] += f0.y;
                acc[mi][ni][2] += f1.x;
                acc[mi][ni][3] += f1.y;
                accH[mi][ni][0] = 0u;
                accH[mi][ni][1] = 0u;
            }
    };

    // prologue: stage 0
    issue(0);
    CP_WAIT0();
    convert(0);
    __syncthreads();

    for (int c = 0; c < 16; ++c) {
        if (c < 15) issue(c + 1);

        // ---- MMAs on stage c&1 ----
        const uint32_t stg = sb + (uint32_t)(c & 1) * STAGE;
#pragma unroll
        for (int ks = 0; ks < 32; ks += 16) {
            const uint32_t a_addr = stg + (uint32_t)(a_row * 80 + (ks + a_col) * 2);
            const uint32_t b_addr = stg + (uint32_t)(b_row * 80 + (ks + b_col) * 2);

            uint32_t ah[4][4], bh[4][4];
#pragma unroll
            for (int mi = 0; mi < 4; ++mi) ldsm4(ah[mi], a_addr + OFF_AT + mi * 16 * 80);
#pragma unroll
            for (int q = 0; q < 4; ++q)    ldsm4(bh[q], b_addr + OFF_BT + q * 16 * 80);
#pragma unroll
            for (int mi = 0; mi < 4; ++mi)
#pragma unroll
                for (int ni = 0; ni < 8; ++ni)
                    mma16816h(accH[mi][ni], ah[mi], bh[ni >> 1][(ni & 1) * 2],
                              bh[ni >> 1][(ni & 1) * 2 + 1]);
        }

        if (c & 1) promote();   // every 2 chunks = K 64 in f16 partials

        if (c < 15) {
            CP_WAIT0();
            convert(c + 1);
        }
        __syncthreads();
    }

    // ---- epilogue: add db, store fp32 delta ----
#pragma unroll
    for (int ni = 0; ni < 8; ++ni) {
        int colL = wn * 64 + ni * 8 + ((lane & 3) << 1);
        int col  = ntile + colL;
        float db0 = db_s[colL];
        float db1 = db_s[colL + 1];
#pragma unroll
        for (int mi = 0; mi < 4; ++mi) {
            int row = wm * 64 + mi * 16 + (lane >> 2);
            float2 v0 = make_float2(acc[mi][ni][0] + db0, acc[mi][ni][1] + db1);
            float2 v1 = make_float2(acc[mi][ni][2] + db0, acc[mi][ni][3] + db1);
            *reinterpret_cast<float2*>(&g_S[(size_t)row * NPAD + col]) = v0;
            *reinterpret_cast<float2*>(&g_S[(size_t)(row + 8) * NPAD + col]) = v1;
        }
    }
}

// ---------------------------------------------------------------------------
// Warp-autonomous tree: each warp owns a depth-8 subtree (64 leaves).
// No smem, no barriers. Grid (32, 256), block 256 = 8 warps.
// ---------------------------------------------------------------------------
__device__ __forceinline__ void sig2(float delta, float& p0, float& p1) {
    float dc = fminf(fmaxf(delta, -30.f), 30.f);
    float t = __expf(-dc);
    float r = __fdividef(1.f, 1.f + t);
    p1 = r;
    p0 = t * r;
}

__global__ void __launch_bounds__(256) tree_kernel(float* __restrict__ out) {
    const int warp = threadIdx.x >> 5;
    const int lane = threadIdx.x & 31;
    const int t    = blockIdx.x * 8 + warp;   // depth-8 subtree index 0..255
    const int b    = blockIdx.y;              // batch row
    const float* S = g_S + (size_t)b * NPAD;

    // ---- path prefix through depths 0..7 (lane d computes ancestor d) ----
    float v = 1.f;
    if (lane < 8) {
        int d    = lane;
        int node = ((256 + t) >> (8 - d)) - 1;
        int bit  = (t >> (7 - d)) & 1;
        float p0, p1;
        sig2(S[node], p0, p1);
        v = bit ? p1 : p0;
    }
    v *= __shfl_xor_sync(0xFFFFFFFFu, v, 1);
    v *= __shfl_xor_sync(0xFFFFFFFFu, v, 2);
    v *= __shfl_xor_sync(0xFFFFFFFFu, v, 4);
    float cur = __shfl_sync(0xFFFFFFFFu, v, 0);   // prefix at depth-8 node t

    // ---- expand depths 8..12 via shuffles ----
#pragma unroll
    for (int k = 0; k < 5; ++k) {
        const int L    = 1 << k;                              // nodes this level
        const int base = ((1 << (8 + k)) - 1) + t * L;
        float p0, p1;
        sig2(S[base + (lane < L ? lane : 0)], p0, p1);        // lanes >= L: dummy
        int parent = lane >> 1;
        float c  = __shfl_sync(0xFFFFFFFFu, cur, parent);
        float a0 = __shfl_sync(0xFFFFFFFFu, p0,  parent);
        float a1 = __shfl_sync(0xFFFFFFFFu, p1,  parent);
        cur = c * ((lane & 1) ? a1 : a0);                     // valid for lane < 2L
    }

    // ---- depth 13: 32 nodes, write 64 leaves ----
    const int nbase = 8191 + t * 32;
    float p0, p1;
    sig2(S[nbase + lane], p0, p1);
    float2 leaf = make_float2(cur * p0, cur * p1);
    *reinterpret_cast<float2*>(out + (size_t)b * NPAD + t * 64 + lane * 2) = leaf;
}

// ---------------------------------------------------------------------------
// Launch
// ---------------------------------------------------------------------------
extern "C" void kernel_launch(void* const* d_in, const int* in_sizes, int n_in,
                              void* d_out, int out_size) {
    const float* x    = (const float*)d_in[0];
    const float* W    = (const float*)d_in[1];
    const float* bvec = (const float*)d_in[2];
    float* out = (float*)d_out;

    cudaFuncSetAttribute(gemm_f, cudaFuncAttributeMaxDynamicSharedMemorySize, GEMM_SMEM);

    gemm_f<<<128, 256, GEMM_SMEM>>>(x, W, bvec);
    tree_kernel<<<dim3(32, BATCH), 256>>>(out);
}

// round 17
// speedup vs baseline: 1.2273x; 1.2273x over previous
#include <cuda_runtime.h>
#include <cuda_fp16.h>
#include <cstdint>

#define BATCH  256
#define EDIM   512
#define NNODES 16383
#define NPAD   16384

// ---------------------------------------------------------------------------
// Scratch (static device globals: allocation-free rule)
// ---------------------------------------------------------------------------
__device__ float g_S[BATCH * NPAD];   // delta logits

// ---------------------------------------------------------------------------
// cp.async + ldmatrix helpers
// ---------------------------------------------------------------------------
__device__ __forceinline__ uint32_t smem_u32(const void* p) {
    uint32_t a;
    asm("{ .reg .u64 t; cvta.to.shared.u64 t, %1; cvt.u32.u64 %0, t; }" : "=r"(a) : "l"(p));
    return a;
}
__device__ __forceinline__ void cp16(uint32_t dst, const void* src) {
    asm volatile("cp.async.ca.shared.global [%0], [%1], 16;" :: "r"(dst), "l"(src));
}
__device__ __forceinline__ void cp16z(uint32_t dst, const void* src, uint32_t src_bytes) {
    asm volatile("cp.async.ca.shared.global [%0], [%1], 16, %2;"
                 :: "r"(dst), "l"(src), "r"(src_bytes));
}
#define CP_COMMIT() asm volatile("cp.async.commit_group;" ::: "memory")
#define CP_WAIT0()  asm volatile("cp.async.wait_group 0;" ::: "memory")

__device__ __forceinline__ void ldsm4(uint32_t* r, uint32_t addr) {
    asm volatile("ldmatrix.sync.aligned.m8n8.x4.shared.b16 {%0,%1,%2,%3}, [%4];"
                 : "=r"(r[0]), "=r"(r[1]), "=r"(r[2]), "=r"(r[3]) : "r"(addr));
}

__device__ __forceinline__ void mma16816(float* acc, const uint32_t* a, uint32_t b0, uint32_t b1) {
    asm volatile(
        "mma.sync.aligned.m16n8k16.row.col.f32.f16.f16.f32 "
        "{%0,%1,%2,%3}, {%4,%5,%6,%7}, {%8,%9}, {%0,%1,%2,%3};\n"
        : "+f"(acc[0]), "+f"(acc[1]), "+f"(acc[2]), "+f"(acc[3])
        : "r"(a[0]), "r"(a[1]), "r"(a[2]), "r"(a[3]), "r"(b0), "r"(b1));
}

// ---------------------------------------------------------------------------
// Fully-fused single-phase fp16 GEMM (f32 acc): S = fp16(x) . fp16(dW) + db
//   512 threads / 16 warps; warp tile 64(M) x 32(N). Block M=256 x N=128.
//   K = 512 in 16 chunks of 32. Per chunk: cp.async raw x + raw W f32,
//   convert both to fp16 tiles in SMEM, 1 mma phase. 2-stage ring.
//   (R10 design — measured 27.0 us, rel_err 5.33e-4.)
// ---------------------------------------------------------------------------
#define STAGE     96256
#define OFF_AT    0          // A fp16 tile: 256 x 40 (pitch 80 B) = 20480
#define OFF_BT    20480      // B fp16 tile: 128 x 40 = 10240
#define OFF_XR    30720      // raw x: 256 rows x 32 f32 = 32768
#define OFF_WR    63488      // raw W: 128 nodes x 64 f32 = 32768
#define OFF_DB    (2 * STAGE)            // 192512
#define GEMM_SMEM (OFF_DB + 512)         // 193024 B

__global__ void __launch_bounds__(512) gemm_f(const float* __restrict__ x,
                                              const float* __restrict__ W,
                                              const float* __restrict__ bvec) {
    extern __shared__ char smem[];
    const uint32_t sb = smem_u32(smem);
    const int tid  = threadIdx.x;
    const int lane = tid & 31;
    const int warp = tid >> 5;
    const int wm   = warp >> 2;   // 0..3 -> M base wm*64
    const int wn   = warp & 3;    // 0..3 -> N base wn*32
    const int ntile = blockIdx.x * 128;

    float* db_s = reinterpret_cast<float*>(smem + OFF_DB);
    if (tid < 128) {
        int col = ntile + tid;
        db_s[tid] = (col < NNODES) ? (bvec[2 * col + 1] - bvec[2 * col]) : 0.f;
    }

    float acc[4][4][4];
#pragma unroll
    for (int mi = 0; mi < 4; ++mi)
#pragma unroll
        for (int ni = 0; ni < 4; ++ni)
#pragma unroll
            for (int q = 0; q < 4; ++q) acc[mi][ni][q] = 0.f;

    const int a_row = wm * 64 + (lane & 7) + ((lane >> 3) & 1) * 8;
    const int a_col = (lane >> 4) * 8;
    const int b_row = wn * 32 + (lane & 7) + ((lane >> 4) & 1) * 8;
    const int b_col = ((lane >> 3) & 1) * 8;

    auto issue = [&](int c) {
        const uint32_t stg = sb + (uint32_t)(c & 1) * STAGE;
        // raw x: 256 rows x 32 f32 (8 x 16 B) = 2048 cp16, 4/thread
#pragma unroll
        for (int j = 0; j < 4; ++j) {
            int u  = tid + 512 * j;
            int row = u >> 3;
            int q8  = u & 7;
            const char* src = reinterpret_cast<const char*>(x) +
                              (size_t)row * 2048 + c * 128 + q8 * 16;
            cp16(stg + OFF_XR + u * 16, src);
        }
        // raw W: 128 nodes x 64 f32 (16 x 16 B) = 2048 cp16, 4/thread
#pragma unroll
        for (int j = 0; j < 4; ++j) {
            int p  = tid + 512 * j;
            int nl = p >> 4;
            int e2 = p & 15;
            int ng = ntile + nl;
            int ok = (ng < NNODES);
            const char* src = reinterpret_cast<const char*>(
                W + (size_t)(ok ? ng : 0) * 1024 + c * 64) + e2 * 16;
            cp16z(stg + OFF_WR + p * 16, src, ok ? 16u : 0u);
        }
        CP_COMMIT();
    };

    auto convert = [&](int c) {
        char* base = smem + (size_t)(c & 1) * STAGE;
#pragma unroll
        for (int j = 0; j < 4; ++j) {
            int u  = tid + 512 * j;
            int row = u >> 3;
            int q8  = u & 7;
            float4 v = *reinterpret_cast<const float4*>(base + OFF_XR + u * 16);
            __half2 p0 = __halves2half2(__float2half_rn(v.x), __float2half_rn(v.y));
            __half2 p1 = __halves2half2(__float2half_rn(v.z), __float2half_rn(v.w));
            __half2* dst = reinterpret_cast<__half2*>(base + OFF_AT + row * 80 + q8 * 8);
            dst[0] = p0;
            dst[1] = p1;
        }
#pragma unroll
        for (int j = 0; j < 4; ++j) {
            int p  = tid + 512 * j;
            int nl = p >> 4;
            int e2 = p & 15;
            float4 w = *reinterpret_cast<const float4*>(base + OFF_WR + p * 16);
            __half h0 = __float2half_rn(w.y - w.x);
            __half h1 = __float2half_rn(w.w - w.z);
            *reinterpret_cast<__half2*>(base + OFF_BT + nl * 80 + e2 * 4) =
                __halves2half2(h0, h1);
        }
    };

    issue(0);
    CP_WAIT0();
    convert(0);
    __syncthreads();

    for (int c = 0; c < 16; ++c) {
        if (c < 15) issue(c + 1);

        const uint32_t stg = sb + (uint32_t)(c & 1) * STAGE;
#pragma unroll
        for (int ks = 0; ks < 32; ks += 16) {
            const uint32_t a_addr = stg + (uint32_t)(a_row * 80 + (ks + a_col) * 2);
            const uint32_t b_addr = stg + (uint32_t)(b_row * 80 + (ks + b_col) * 2);

            uint32_t ah[4][4], bh[2][4];
#pragma unroll
            for (int mi = 0; mi < 4; ++mi) ldsm4(ah[mi], a_addr + OFF_AT + mi * 16 * 80);
#pragma unroll
            for (int q = 0; q < 2; ++q)    ldsm4(bh[q], b_addr + OFF_BT + q * 16 * 80);
#pragma unroll
            for (int mi = 0; mi < 4; ++mi)
#pragma unroll
                for (int ni = 0; ni < 4; ++ni)
                    mma16816(acc[mi][ni], ah[mi], bh[ni >> 1][(ni & 1) * 2],
                             bh[ni >> 1][(ni & 1) * 2 + 1]);
        }

        if (c < 15) {
            CP_WAIT0();
            convert(c + 1);
        }
        __syncthreads();
    }

#pragma unroll
    for (int ni = 0; ni < 4; ++ni) {
        int colL = wn * 32 + ni * 8 + ((lane & 3) << 1);
        int col  = ntile + colL;
        float db0 = db_s[colL];
        float db1 = db_s[colL + 1];
#pragma unroll
        for (int mi = 0; mi < 4; ++mi) {
            int row = wm * 64 + mi * 16 + (lane >> 2);
            float2 v0 = make_float2(acc[mi][ni][0] + db0, acc[mi][ni][1] + db1);
            float2 v1 = make_float2(acc[mi][ni][2] + db0, acc[mi][ni][3] + db1);
            *reinterpret_cast<float2*>(&g_S[(size_t)row * NPAD + col]) = v0;
            *reinterpret_cast<float2*>(&g_S[(size_t)(row + 8) * NPAD + col]) = v1;
        }
    }
}

// ---------------------------------------------------------------------------
// Tree v3: warp-autonomous, 3 sig2 batches (internal / prefix / leaves).
// Internal node probs pre-computed once across lanes; expansion ladder is
// pure shfl+mul. Each warp owns a depth-8 subtree (64 leaves).
// Grid (32, 256), block 256 = 8 warps; no smem, no barriers.
// ---------------------------------------------------------------------------
__device__ __forceinline__ void sig2(float delta, float& p0, float& p1) {
    float dc = fminf(fmaxf(delta, -30.f), 30.f);
    float t = __expf(-dc);
    float r = __fdividef(1.f, 1.f + t);
    p1 = r;
    p0 = t * r;
}

__global__ void __launch_bounds__(256) tree_kernel(float* __restrict__ out) {
    const int warp = threadIdx.x >> 5;
    const int lane = threadIdx.x & 31;
    const int t    = blockIdx.x * 8 + warp;   // depth-8 subtree index 0..255
    const int b    = blockIdx.y;              // batch row
    const float* S = g_S + (size_t)b * NPAD;

    // ---- batch 1: internal probs (depths 8..12 of subtree t) ----
    // lane L -> level k = floor(log2(L+1)), global node g = ((255+t)<<k) + L
    // lanes 0..30 cover all 31 internal nodes; lane 31 loads an in-bounds
    // leaf-level node (unused).
    const int k = 31 - __clz(lane + 1);
    const int g = ((255 + t) << k) + lane;
    float P0, P1;
    sig2(S[g], P0, P1);

    // ---- batch 2: prefix through depths 0..7 ----
    float v = 1.f;
    if (lane < 8) {
        int d    = lane;
        int node = ((256 + t) >> (8 - d)) - 1;
        int bit  = (t >> (7 - d)) & 1;
        float q0, q1;
        sig2(S[node], q0, q1);
        v = bit ? q1 : q0;
    }
    v *= __shfl_xor_sync(0xFFFFFFFFu, v, 1);
    v *= __shfl_xor_sync(0xFFFFFFFFu, v, 2);
    v *= __shfl_xor_sync(0xFFFFFFFFu, v, 4);
    float cur = __shfl_sync(0xFFFFFFFFu, v, 0);   // prefix at depth-8 node t

    // ---- ladder: expand depths 8..12 using pre-computed probs ----
    // After step kk, cur valid for lanes < 2^(kk+1). Prob of level-kk parent
    // (lane>>1) lives at lane (2^kk - 1) + (lane>>1).
#pragma unroll
    for (int kk = 0; kk < 5; ++kk) {
        int half  = lane >> 1;
        int plane = (1 << kk) - 1 + half;
        float c  = __shfl_sync(0xFFFFFFFFu, cur, half);
        float a0 = __shfl_sync(0xFFFFFFFFu, P0, plane);
        float a1 = __shfl_sync(0xFFFFFFFFu, P1, plane);
        cur = c * ((lane & 1) ? a1 : a0);
    }

    // ---- batch 3: depth-13 probs, write 64 leaves ----
    float p0, p1;
    sig2(S[8191 + t * 32 + lane], p0, p1);
    float2 leaf = make_float2(cur * p0, cur * p1);
    *reinterpret_cast<float2*>(out + (size_t)b * NPAD + t * 64 + lane * 2) = leaf;
}

// ---------------------------------------------------------------------------
// Launch
// ---------------------------------------------------------------------------
extern "C" void kernel_launch(void* const* d_in, const int* in_sizes, int n_in,
                              void* d_out, int out_size) {
    const float* x    = (const float*)d_in[0];
    const float* W    = (const float*)d_in[1];
    const float* bvec = (const float*)d_in[2];
    float* out = (float*)d_out;

    cudaFuncSetAttribute(gemm_f, cudaFuncAttributeMaxDynamicSharedMemorySize, GEMM_SMEM);

    gemm_f<<<128, 512, GEMM_SMEM>>>(x, W, bvec);
    tree_kernel<<<dim3(32, BATCH), 256>>>(out);
}